// round 3
// baseline (speedup 1.0000x reference)
#include <cuda_runtime.h>

// Burden_29145648070955: strategic-training forward path, reduced to
//   s_{t+1} = (X.w + b) + 0.5*||w||^2 * nab(s_t),  output = s_21.
// One streaming matvec over X + per-row scalar recurrence. HBM-bound.
//
// R3: free the 32-reg w fragment (w read via __ldg -> L1-resident 4KB, zero
// DRAM cost) so launch_bounds(128,5) fits 5 CTAs/SM -> 20 warps, raising
// SM-level bytes-in-flight and DRAM duty cycle.

#define BATCH   65536
#define DIM     1024
#define THREADS 128
#define WARPS   (THREADS / 32)
#define ROWS_PER_WARP  32
#define ROWS_PER_BLOCK (WARPS * ROWS_PER_WARP)   // 128
#define GRID   (BATCH / ROWS_PER_BLOCK)          // 512 (single wave @ 5 CTA/SM)
#define NITERS 21                                 // 20 CCP steps + final apply
#define DIM4   (DIM / 4)                          // 256 float4 per row

__device__ __forceinline__ float dot8w(const float4* __restrict__ x,
                                       const float4* __restrict__ w4p,
                                       int lane)
{
    float a = 0.f;
#pragma unroll
    for (int k = 0; k < 8; k++) {
        const float4 wv = __ldg(&w4p[lane + 32 * k]);   // L1 hit after warmup
        a += x[k].x * wv.x + x[k].y * wv.y
           + x[k].z * wv.z + x[k].w * wv.w;
    }
    return a;
}

__global__ void __launch_bounds__(THREADS, 5)
burden_kernel(const float* __restrict__ X,
              const float* __restrict__ w,
              const float* __restrict__ b,
              float* __restrict__ out)
{
    const int lane    = threadIdx.x & 31;
    const int warp    = threadIdx.x >> 5;
    const int rowBase = blockIdx.x * ROWS_PER_BLOCK + warp * ROWS_PER_WARP;

    const float4* w4p = reinterpret_cast<const float4*>(w);

    // ---- ww = ||w||^2 (butterfly, all lanes) ----
    float wwp = 0.f;
#pragma unroll
    for (int k = 0; k < 8; k++) {
        const float4 wv = __ldg(&w4p[lane + 32 * k]);
        wwp += wv.x * wv.x + wv.y * wv.y + wv.z * wv.z + wv.w * wv.w;
    }
#pragma unroll
    for (int o = 16; o > 0; o >>= 1) wwp += __shfl_xor_sync(0xffffffffu, wwp, o);
    const float ww = wwp;
    const float b0 = b[0];

    const float4* base = reinterpret_cast<const float4*>(X)
                       + (size_t)rowBase * DIM4;

    // ---- pipelined row dots: A/B double buffer, loads always in flight ----
    float4 A[8], B[8];
#pragma unroll
    for (int k = 0; k < 8; k++) A[k] = __ldcs(base + lane + 32 * k);  // row 0

    float myS = 0.f;   // lane j ends up holding s0 for row rowBase + j
#pragma unroll 1
    for (int j = 0; j < ROWS_PER_WARP; j += 2) {
        // prefetch row j+1 into B
        const float4* pB = base + (size_t)(j + 1) * DIM4;
#pragma unroll
        for (int k = 0; k < 8; k++) B[k] = __ldcs(pB + lane + 32 * k);

        float a0 = dot8w(A, w4p, lane);       // row j (A resident)

        // prefetch row j+2 into A (off on last iteration)
        if (j + 2 < ROWS_PER_WARP) {
            const float4* pA = base + (size_t)(j + 2) * DIM4;
#pragma unroll
            for (int k = 0; k < 8; k++) A[k] = __ldcs(pA + lane + 32 * k);
        }

        float a1 = dot8w(B, w4p, lane);       // row j+1

        // merged 2-row reduction: 6 shuffles total
        a0 += __shfl_xor_sync(0xffffffffu, a0, 1);
        a1 += __shfl_xor_sync(0xffffffffu, a1, 1);
        float v = (lane & 1) ? a1 : a0;
#pragma unroll
        for (int o = 2; o <= 16; o <<= 1)
            v += __shfl_xor_sync(0xffffffffu, v, o);
        // even lanes hold sum over row j, odd lanes over row j+1
        if ((lane & ~1) == j) myS = v;
    }

    // ---- per-row scalar CCP recurrence, lane-parallel ----
    const float t0 = myS + b0;
    const float c  = 0.5f * ww;
    float s = t0;
#pragma unroll
    for (int it = 0; it < NITERS; it++) {
        float z   = s + 1.0f;                       // slope = 1
        float nab = 0.5f * z * rsqrtf(z * z + 1.0f);
        s = t0 + c * nab;
    }
    out[rowBase + lane] = s;   // coalesced
}

extern "C" void kernel_launch(void* const* d_in, const int* in_sizes, int n_in,
                              void* d_out, int out_size)
{
    const float* X = (const float*)d_in[0];
    const float* w = (const float*)d_in[1];
    const float* b = (const float*)d_in[2];
    float* out = (float*)d_out;
    (void)in_sizes; (void)n_in; (void)out_size;

    burden_kernel<<<GRID, THREADS>>>(X, w, b, out);
}

// round 4
// speedup vs baseline: 1.1518x; 1.1518x over previous
#include <cuda_runtime.h>

// Burden_29145648070955:  output = s_21 of the scalar map
//   s_{t+1} = (X.w + b) + 0.5*||w||^2 * nab(s_t),
// i.e. one streaming matvec over X[65536,1024] + per-row scalar recurrence.
//
// R4: persistent exactly-resident grid (592 CTAs = 148 SMs x 4, 16 warps/SM
// all kernel long, no waves). 2368 warps split rows evenly (28/26, even so
// the 2-row pipeline has no odd tail). Register w, A/B double buffer,
// 4-way split dot accumulators, 6-shuffle pair reduction, lane-parallel
// recurrence.

#define BATCH    65536
#define DIM      1024
#define DIM4     (DIM / 4)      // 256 float4 per row
#define THREADS  128
#define GRID     592            // 148 SMs * 4 CTAs
#define NWARPS   (GRID * 4)     // 2368
#define NBIG     1984           // warps with 28 rows (rest: 26)  28*1984+26*384=65536
#define NITERS   21             // 20 CCP steps + final apply

__device__ __forceinline__ float dot8(const float4* __restrict__ x,
                                      const float4* __restrict__ w)
{
    // 4 independent partials: dependent FFMA chain depth 8 instead of 32
    float p0 = 0.f, p1 = 0.f, p2 = 0.f, p3 = 0.f;
#pragma unroll
    for (int k = 0; k < 8; k++) {
        p0 += x[k].x * w[k].x;
        p1 += x[k].y * w[k].y;
        p2 += x[k].z * w[k].z;
        p3 += x[k].w * w[k].w;
    }
    return (p0 + p1) + (p2 + p3);
}

__global__ void __launch_bounds__(THREADS, 4)
burden_kernel(const float* __restrict__ X,
              const float* __restrict__ w,
              const float* __restrict__ b,
              float* __restrict__ out)
{
    const int lane = threadIdx.x & 31;
    const int warp = threadIdx.x >> 5;
    const int g    = blockIdx.x * 4 + warp;          // global warp id, < NWARPS

    // even row split: warp g gets rows [start, start+cnt)
    const int small = (g < NBIG) ? g : NBIG;
    const int start = 26 * g + 2 * small;            // 28 rows first NBIG warps
    const int cnt   = (g < NBIG) ? 28 : 26;

    // ---- w fragment in registers: lane owns float4 columns lane+32k ----
    const float4* w4p = reinterpret_cast<const float4*>(w);
    float4 w4[8];
#pragma unroll
    for (int k = 0; k < 8; k++) w4[k] = w4p[lane + 32 * k];

    // ---- ww = ||w||^2 (butterfly, all lanes) ----
    float wwp = dot8(w4, w4);
#pragma unroll
    for (int o = 16; o > 0; o >>= 1) wwp += __shfl_xor_sync(0xffffffffu, wwp, o);
    const float ww = wwp;
    const float b0 = b[0];

    const float4* base = reinterpret_cast<const float4*>(X)
                       + (size_t)start * DIM4;

    // ---- pipelined row dots: A/B double buffer ----
    float4 A[8], B[8];
#pragma unroll
    for (int k = 0; k < 8; k++) A[k] = __ldcs(base + lane + 32 * k);  // row 0

    float myS = 0.f;   // lane j ends holding s0 for row start + j
#pragma unroll 1
    for (int j = 0; j < cnt; j += 2) {
        // prefetch row j+1 into B (cnt even -> always valid)
        const float4* pB = base + (size_t)(j + 1) * DIM4;
#pragma unroll
        for (int k = 0; k < 8; k++) B[k] = __ldcs(pB + lane + 32 * k);

        float a0 = dot8(A, w4);               // row j (A resident)

        // prefetch row j+2 into A
        if (j + 2 < cnt) {
            const float4* pA = base + (size_t)(j + 2) * DIM4;
#pragma unroll
            for (int k = 0; k < 8; k++) A[k] = __ldcs(pA + lane + 32 * k);
        }

        float a1 = dot8(B, w4);               // row j+1

        // merged 2-row reduction: 6 shuffles
        a0 += __shfl_xor_sync(0xffffffffu, a0, 1);
        a1 += __shfl_xor_sync(0xffffffffu, a1, 1);
        float v = (lane & 1) ? a1 : a0;
#pragma unroll
        for (int o = 2; o <= 16; o <<= 1)
            v += __shfl_xor_sync(0xffffffffu, v, o);
        // even lanes hold sum(row j), odd lanes sum(row j+1)
        if ((lane & ~1) == j) myS = v;
    }

    // ---- lane-parallel scalar CCP recurrence (one batch per warp) ----
    const float t0 = myS + b0;
    const float c  = 0.5f * ww;
    float s = t0;
#pragma unroll
    for (int it = 0; it < NITERS; it++) {
        float z   = s + 1.0f;                        // slope = 1
        float nab = 0.5f * z * rsqrtf(z * z + 1.0f);
        s = t0 + c * nab;
    }
    if (lane < cnt) out[start + lane] = s;           // contiguous 104/112B store
}

extern "C" void kernel_launch(void* const* d_in, const int* in_sizes, int n_in,
                              void* d_out, int out_size)
{
    const float* X = (const float*)d_in[0];
    const float* w = (const float*)d_in[1];
    const float* b = (const float*)d_in[2];
    float* out = (float*)d_out;
    (void)in_sizes; (void)n_in; (void)out_size;

    burden_kernel<<<GRID, THREADS>>>(X, w, b, out);
}

// round 5
// speedup vs baseline: 1.1822x; 1.0263x over previous
#include <cuda_runtime.h>

// Burden_29145648070955:  output = s_21 of the scalar map
//   s_{t+1} = (X.w + b) + 0.5*||w||^2 * nab(s_t),  nab(z)=0.5*(z+1)/sqrt((z+1)^2+1)
// i.e. one streaming matvec over X[65536,1024] + per-row scalar recurrence.
//
// Converged design: measured 6.4 TB/s across three residency configs = the
// path-independent LTS ceiling; 268 MB / cap ~= 42.6 us floor. R5 trims the
// zero-DRAM prologue (X loads issued BEFORE the w load + ww reduction) and
// peels the loop tail. Otherwise R2 shape: grid 512, 32 rows/warp, A/B
// double buffer, 4-way split dot, 6-shuffle pair reduction.

#define BATCH   65536
#define DIM     1024
#define DIM4    (DIM / 4)       // 256 float4 per row
#define THREADS 128
#define ROWS_PER_WARP  32
#define ROWS_PER_BLOCK 128
#define GRID    (BATCH / ROWS_PER_BLOCK)   // 512
#define NITERS  21                          // 20 CCP steps + final apply

__device__ __forceinline__ float dot8(const float4* __restrict__ x,
                                      const float4* __restrict__ w)
{
    float p0 = 0.f, p1 = 0.f, p2 = 0.f, p3 = 0.f;
#pragma unroll
    for (int k = 0; k < 8; k++) {
        p0 += x[k].x * w[k].x;
        p1 += x[k].y * w[k].y;
        p2 += x[k].z * w[k].z;
        p3 += x[k].w * w[k].w;
    }
    return (p0 + p1) + (p2 + p3);
}

__global__ void __launch_bounds__(THREADS, 4)
burden_kernel(const float* __restrict__ X,
              const float* __restrict__ w,
              const float* __restrict__ b,
              float* __restrict__ out)
{
    const int lane    = threadIdx.x & 31;
    const int warp    = threadIdx.x >> 5;
    const int rowBase = blockIdx.x * ROWS_PER_BLOCK + warp * ROWS_PER_WARP;

    const float4* base = reinterpret_cast<const float4*>(X)
                       + (size_t)rowBase * DIM4;

    // ---- X loads FIRST: rows 0 and 1 in flight before any w work ----
    float4 A[8], B[8];
#pragma unroll
    for (int k = 0; k < 8; k++) A[k] = __ldcs(base + lane + 32 * k);
#pragma unroll
    for (int k = 0; k < 8; k++) B[k] = __ldcs(base + DIM4 + lane + 32 * k);

    // ---- w fragment + ww reduction, overlapped with the X flight time ----
    const float4* w4p = reinterpret_cast<const float4*>(w);
    float4 w4[8];
#pragma unroll
    for (int k = 0; k < 8; k++) w4[k] = w4p[lane + 32 * k];

    float wwp = dot8(w4, w4);
#pragma unroll
    for (int o = 16; o > 0; o >>= 1) wwp += __shfl_xor_sync(0xffffffffu, wwp, o);
    const float ww = wwp;
    const float b0 = b[0];

    float myS = 0.f;   // lane j ends holding s0 for row rowBase + j

    // ---- steady state: rows j,j+1 resident; prefetch j+2,j+3 ----
#pragma unroll 1
    for (int j = 0; j < ROWS_PER_WARP - 2; j += 2) {
        float a0 = dot8(A, w4);

        const float4* pA = base + (size_t)(j + 2) * DIM4;
#pragma unroll
        for (int k = 0; k < 8; k++) A[k] = __ldcs(pA + lane + 32 * k);

        float a1 = dot8(B, w4);

        const float4* pB = base + (size_t)(j + 3) * DIM4;
#pragma unroll
        for (int k = 0; k < 8; k++) B[k] = __ldcs(pB + lane + 32 * k);

        // merged 2-row reduction: 6 shuffles
        a0 += __shfl_xor_sync(0xffffffffu, a0, 1);
        a1 += __shfl_xor_sync(0xffffffffu, a1, 1);
        float v = (lane & 1) ? a1 : a0;
#pragma unroll
        for (int o = 2; o <= 16; o <<= 1)
            v += __shfl_xor_sync(0xffffffffu, v, o);
        if ((lane & ~1) == j) myS = v;       // even lane: row j, odd: row j+1
    }

    // ---- peeled last pair (rows 30, 31) ----
    {
        const int j = ROWS_PER_WARP - 2;
        float a0 = dot8(A, w4);
        float a1 = dot8(B, w4);
        a0 += __shfl_xor_sync(0xffffffffu, a0, 1);
        a1 += __shfl_xor_sync(0xffffffffu, a1, 1);
        float v = (lane & 1) ? a1 : a0;
#pragma unroll
        for (int o = 2; o <= 16; o <<= 1)
            v += __shfl_xor_sync(0xffffffffu, v, o);
        if ((lane & ~1) == j) myS = v;
    }

    // ---- lane-parallel scalar CCP recurrence ----
    const float t0 = myS + b0;
    const float c  = 0.5f * ww;
    float s = t0;
#pragma unroll
    for (int it = 0; it < NITERS; it++) {
        float z   = s + 1.0f;                        // slope = 1
        float nab = 0.5f * z * rsqrtf(z * z + 1.0f);
        s = t0 + c * nab;
    }
    out[rowBase + lane] = s;   // coalesced 128B per warp
}

extern "C" void kernel_launch(void* const* d_in, const int* in_sizes, int n_in,
                              void* d_out, int out_size)
{
    const float* X = (const float*)d_in[0];
    const float* w = (const float*)d_in[1];
    const float* b = (const float*)d_in[2];
    float* out = (float*)d_out;
    (void)in_sizes; (void)n_in; (void)out_size;

    burden_kernel<<<GRID, THREADS>>>(X, w, b, out);
}